// round 12
// baseline (speedup 1.0000x reference)
#include <cuda_runtime.h>
#include <mma.h>
#include <cstdint>

using namespace nvcuda;

#define N_NODES 50000
#define D_IN    128
#define D_OUT   64

// h scratch: h[row][c] = g_h4[row*16 + c/4]
__device__ float4 g_h4[N_NODES * (D_OUT / 4)];
// CSR row starts
__device__ int g_row_start[N_NODES + 1];

// ---------------------------------------------------------------------------
// Kernel 1: h = x @ W via tf32 mma.sync, operands staged in smem, PLUS the
// CSR row_start fill folded into the kernel tail (edge-scan, 4 edges/thread
// iteration). The fill's memory latency hides under other blocks' MMA work,
// removing the dedicated fill launch and its ~6-12us latency floor.
//   xs: [128][132] tf32 (A row-major, ld=132 -> conflict-free)
//   wt: [64][132]  tf32 (B=W^T col-major frag, ld=132 -> conflict-free)
// Block: 256 thr / 8 warps, 128 rows; warp w owns rows [16w,16w+16) x 64 cols.
// ---------------------------------------------------------------------------
#define XS_LD 132
#define WT_LD 132
#define SMEM_WT_OFF (128 * XS_LD)                       // floats
#define GEMM_SMEM   ((128 * XS_LD + 64 * WT_LD) * 4)    // 101376 B

__global__ __launch_bounds__(256) void gemm_fill_kernel(
    const float* __restrict__ x,
    const float* __restrict__ w,
    float* __restrict__ h,
    const int* __restrict__ dst,
    int* __restrict__ row_start,
    int n_nodes, int n_edges)
{
    extern __shared__ float sm[];
    float* xs = sm;                  // [128][XS_LD]
    float* wt = sm + SMEM_WT_OFF;    // [64][WT_LD], wt[n][k]

    const int tid = threadIdx.x;
    const int wid = tid >> 5;
    const int row0 = blockIdx.x * 128;

    // ---- stage W^T ----
    #pragma unroll
    for (int i = tid; i < D_IN * D_OUT; i += 256) {
        int k = i >> 6, n = i & 63;
        wt[n * WT_LD + k] = wmma::__float_to_tf32(w[i]);
    }
    // ---- stage x tile ----
    {
        const float4* x4 = (const float4*)x;
        #pragma unroll
        for (int i = tid; i < 128 * 32; i += 256) {
            int r = i >> 5, c4 = i & 31;
            if (row0 + r < n_nodes) {
                float4 v = x4[(size_t)(row0 + r) * 32 + c4];
                float* p = xs + r * XS_LD + c4 * 4;
                p[0] = wmma::__float_to_tf32(v.x);
                p[1] = wmma::__float_to_tf32(v.y);
                p[2] = wmma::__float_to_tf32(v.z);
                p[3] = wmma::__float_to_tf32(v.w);
            }
        }
    }
    __syncthreads();

    // ---- tensor-core GEMM ----
    const int wrow = row0 + wid * 16;
    if (wrow < n_nodes) {            // 50000 % 16 == 0: all-or-nothing tiles
        wmma::fragment<wmma::accumulator, 16, 16, 8, float> c[4];
        #pragma unroll
        for (int n = 0; n < 4; n++) wmma::fill_fragment(c[n], 0.0f);

        const float* a_base = xs + wid * 16 * XS_LD;

        #pragma unroll
        for (int k = 0; k < 16; k++) {
            wmma::fragment<wmma::matrix_a, 16, 16, 8, wmma::precision::tf32, wmma::row_major> a;
            wmma::load_matrix_sync(a, a_base + k * 8, XS_LD);
            #pragma unroll
            for (int n = 0; n < 4; n++) {
                wmma::fragment<wmma::matrix_b, 16, 16, 8, wmma::precision::tf32, wmma::col_major> b;
                wmma::load_matrix_sync(b, wt + (n * 16) * WT_LD + k * 8, WT_LD);
                wmma::mma_sync(c[n], a, b, c[n]);
            }
        }

        float* hp = h + (size_t)wrow * D_OUT;
        #pragma unroll
        for (int n = 0; n < 4; n++)
            wmma::store_matrix_sync(hp + n * 16, c[n], D_OUT, wmma::mem_row_major);
    }

    // ---- folded CSR fill: each thread scans quads of sorted dst ----
    // row_start[i] = first e with dst[e] >= i; row_start[n_nodes] = E.
    {
        const int n_threads = gridDim.x * blockDim.x;
        const int n_quads = n_edges >> 2;             // n_edges % 4 == 0
        for (int q = blockIdx.x * blockDim.x + tid; q < n_quads; q += n_threads) {
            int e0 = q * 4;
            int4 v = __ldg((const int4*)(dst + e0));
            int prev = (e0 == 0) ? -1 : __ldg(&dst[e0 - 1]);
            int d[4] = {v.x, v.y, v.z, v.w};
            #pragma unroll
            for (int j = 0; j < 4; j++) {
                for (int i = prev + 1; i <= d[j]; i++) row_start[i] = e0 + j;
                prev = d[j];
            }
            if (e0 + 4 >= n_edges)
                for (int i = prev + 1; i <= n_nodes; i++) row_start[i] = n_edges;
        }
    }
}

// ---------------------------------------------------------------------------
// Kernel 2: aggregation, warp per node, shfl-broadcast metadata.
// Per 32-edge chunk: lanes load (src,val) coalesced into registers; then
// halves iterate (half 0: even j, half 1: odd j), shfl-broadcasting the
// edge's (src,val) so the h-gather is the only dependent load. f4 = lane&15.
// ---------------------------------------------------------------------------
__global__ __launch_bounds__(256) void agg_kernel(
    const float4* __restrict__ h4,
    const int*    __restrict__ src,
    const float*  __restrict__ val,
    const int*    __restrict__ row_start,
    const float4* __restrict__ bias4,
    float4*       __restrict__ out4,
    int n_nodes)
{
    const int lane = threadIdx.x & 31;
    const int f4   = lane & 15;
    const int half = lane >> 4;
    const int node = (blockIdx.x * blockDim.x + threadIdx.x) >> 5;
    if (node >= n_nodes) return;

    const int s = __ldg(&row_start[node]);
    const int t = __ldg(&row_start[node + 1]);

    float4 acc = make_float4(0.f, 0.f, 0.f, 0.f);

    for (int base = s; base < t; base += 32) {
        const int cnt = min(32, t - base);
        const int e   = base + lane;
        float v  = 0.f;
        int   sc = 0;
        if (e < t) { v = __ldg(&val[e]); sc = __ldg(&src[e]); }  // coalesced

        const int iters = (cnt + 1) >> 1;
        #pragma unroll 4
        for (int jj = 0; jj < iters; jj++) {
            const int j = (jj << 1) | half;                      // <= 31
            float vj  = __shfl_sync(0xffffffffu, v,  j);
            int   scj = __shfl_sync(0xffffffffu, sc, j);
            if (j < cnt) {                                       // uniform per half
                float4 hv = __ldg(&h4[(size_t)scj * 16 + f4]);
                acc.x += vj * hv.x; acc.y += vj * hv.y;
                acc.z += vj * hv.z; acc.w += vj * hv.w;
            }
        }
    }

    acc.x += __shfl_xor_sync(0xffffffffu, acc.x, 16);
    acc.y += __shfl_xor_sync(0xffffffffu, acc.y, 16);
    acc.z += __shfl_xor_sync(0xffffffffu, acc.z, 16);
    acc.w += __shfl_xor_sync(0xffffffffu, acc.w, 16);

    if (half == 0) {
        float4 b = __ldg(&bias4[f4]);
        acc.x += b.x; acc.y += b.y; acc.z += b.z; acc.w += b.w;
        out4[(size_t)node * 16 + f4] = acc;
    }
}

// ---------------------------------------------------------------------------
extern "C" void kernel_launch(void* const* d_in, const int* in_sizes, int n_in,
                              void* d_out, int out_size)
{
    const float* x    = (const float*)d_in[0];   // [N, 128]
    const int*   esrc = (const int*)  d_in[1];   // [E]
    const int*   edst = (const int*)  d_in[2];   // [E]
    const float* eval = (const float*)d_in[3];   // [E]
    const float* w    = (const float*)d_in[4];   // [128, 64]
    const float* bias = (const float*)d_in[5];   // [64]
    float* out = (float*)d_out;                  // [N, 64]

    const int n_nodes = in_sizes[0] / D_IN;
    const int n_edges = in_sizes[1];

    float4* h4;
    cudaGetSymbolAddress((void**)&h4, g_h4);
    int* row_start;
    cudaGetSymbolAddress((void**)&row_start, g_row_start);

    // 1) h = x @ W  +  folded row_start fill
    {
        cudaFuncSetAttribute(gemm_fill_kernel,
                             cudaFuncAttributeMaxDynamicSharedMemorySize, GEMM_SMEM);
        int blocks = (n_nodes + 127) / 128;
        gemm_fill_kernel<<<blocks, 256, GEMM_SMEM>>>(x, w, (float*)h4, edst,
                                                     row_start, n_nodes, n_edges);
    }

    // 2) out = bias + A @ h (warp per node, shfl-broadcast metadata)
    {
        size_t threads = (size_t)n_nodes * 32;
        agg_kernel<<<(unsigned)((threads + 255) / 256), 256>>>(
            h4, esrc, eval, row_start, (const float4*)bias, (float4*)out, n_nodes);
    }
}

// round 13
// speedup vs baseline: 1.0213x; 1.0213x over previous
#include <cuda_runtime.h>
#include <mma.h>
#include <cstdint>

using namespace nvcuda;

#define N_NODES 50000
#define D_IN    128
#define D_OUT   64

// h scratch: h[row][c] = g_h4[row*16 + c/4]
__device__ float4 g_h4[N_NODES * (D_OUT / 4)];
// CSR row starts
__device__ int g_row_start[N_NODES + 1];

// ---------------------------------------------------------------------------
// Kernel 1: h = x @ W via tf32 mma.sync, operands staged in smem.
//   xs: [128][132] tf32 (A row-major, ld=132 -> conflict-free)
//   wt: [64][132]  tf32 (B=W^T col-major frag, ld=132 -> conflict-free)
// Block: 256 thr / 8 warps, 128 rows; warp w owns rows [16w,16w+16) x 64 cols.
// ---------------------------------------------------------------------------
#define XS_LD 132
#define WT_LD 132
#define SMEM_WT_OFF (128 * XS_LD)                       // floats
#define GEMM_SMEM   ((128 * XS_LD + 64 * WT_LD) * 4)    // 101376 B

__global__ __launch_bounds__(256) void gemm_tc_kernel(
    const float* __restrict__ x,
    const float* __restrict__ w,
    float* __restrict__ h,
    int n_nodes)
{
    extern __shared__ float sm[];
    float* xs = sm;                  // [128][XS_LD]
    float* wt = sm + SMEM_WT_OFF;    // [64][WT_LD], wt[n][k]

    const int tid = threadIdx.x;
    const int wid = tid >> 5;
    const int row0 = blockIdx.x * 128;

    #pragma unroll
    for (int i = tid; i < D_IN * D_OUT; i += 256) {
        int k = i >> 6, n = i & 63;
        wt[n * WT_LD + k] = wmma::__float_to_tf32(w[i]);
    }
    {
        const float4* x4 = (const float4*)x;
        #pragma unroll
        for (int i = tid; i < 128 * 32; i += 256) {
            int r = i >> 5, c4 = i & 31;
            if (row0 + r < n_nodes) {
                float4 v = x4[(size_t)(row0 + r) * 32 + c4];
                float* p = xs + r * XS_LD + c4 * 4;
                p[0] = wmma::__float_to_tf32(v.x);
                p[1] = wmma::__float_to_tf32(v.y);
                p[2] = wmma::__float_to_tf32(v.z);
                p[3] = wmma::__float_to_tf32(v.w);
            }
        }
    }
    __syncthreads();

    const int wrow = row0 + wid * 16;
    if (wrow >= n_nodes) return;    // 50000 % 16 == 0

    wmma::fragment<wmma::accumulator, 16, 16, 8, float> c[4];
    #pragma unroll
    for (int n = 0; n < 4; n++) wmma::fill_fragment(c[n], 0.0f);

    const float* a_base = xs + wid * 16 * XS_LD;

    #pragma unroll
    for (int k = 0; k < 16; k++) {
        wmma::fragment<wmma::matrix_a, 16, 16, 8, wmma::precision::tf32, wmma::row_major> a;
        wmma::load_matrix_sync(a, a_base + k * 8, XS_LD);
        #pragma unroll
        for (int n = 0; n < 4; n++) {
            wmma::fragment<wmma::matrix_b, 16, 16, 8, wmma::precision::tf32, wmma::col_major> b;
            wmma::load_matrix_sync(b, wt + (n * 16) * WT_LD + k * 8, WT_LD);
            wmma::mma_sync(c[n], a, b, c[n]);
        }
    }

    float* hp = h + (size_t)wrow * D_OUT;
    #pragma unroll
    for (int n = 0; n < 4; n++)
        wmma::store_matrix_sync(hp + n * 16, c[n], D_OUT, wmma::mem_row_major);
}

// ---------------------------------------------------------------------------
// Kernel 2: build row_start from sorted dst. int4-vectorized: 4 edges/thread.
// Runs on a SIDE STREAM concurrently with the gemm (disjoint data).
// ---------------------------------------------------------------------------
__global__ void fill_rowstart_kernel(const int* __restrict__ dst,
                                     int* __restrict__ row_start,
                                     int n_edges, int n_nodes)
{
    int q = blockIdx.x * blockDim.x + threadIdx.x;   // quad index
    int e0 = q * 4;
    if (e0 >= n_edges) return;

    int4 v = __ldg((const int4*)(dst + e0));         // n_edges % 4 == 0
    int prev = (e0 == 0) ? -1 : __ldg(&dst[e0 - 1]);

    int d[4] = {v.x, v.y, v.z, v.w};
    #pragma unroll
    for (int j = 0; j < 4; j++) {
        for (int i = prev + 1; i <= d[j]; i++) row_start[i] = e0 + j;
        prev = d[j];
    }
    if (e0 + 4 >= n_edges)
        for (int i = prev + 1; i <= n_nodes; i++) row_start[i] = n_edges;
}

// ---------------------------------------------------------------------------
// Kernel 3: aggregation, warp per node, shfl-broadcast metadata (measured
// 25.8us). Per 32-edge chunk: lanes load (src,val) coalesced; halves iterate
// broadcasting the edge so the h-gather is the only dependent load.
// ---------------------------------------------------------------------------
__global__ __launch_bounds__(256) void agg_kernel(
    const float4* __restrict__ h4,
    const int*    __restrict__ src,
    const float*  __restrict__ val,
    const int*    __restrict__ row_start,
    const float4* __restrict__ bias4,
    float4*       __restrict__ out4,
    int n_nodes)
{
    const int lane = threadIdx.x & 31;
    const int f4   = lane & 15;
    const int half = lane >> 4;
    const int node = (blockIdx.x * blockDim.x + threadIdx.x) >> 5;
    if (node >= n_nodes) return;

    const int s = __ldg(&row_start[node]);
    const int t = __ldg(&row_start[node + 1]);

    float4 acc = make_float4(0.f, 0.f, 0.f, 0.f);

    for (int base = s; base < t; base += 32) {
        const int cnt = min(32, t - base);
        const int e   = base + lane;
        float v  = 0.f;
        int   sc = 0;
        if (e < t) { v = __ldg(&val[e]); sc = __ldg(&src[e]); }  // coalesced

        const int iters = (cnt + 1) >> 1;
        #pragma unroll 4
        for (int jj = 0; jj < iters; jj++) {
            const int j = (jj << 1) | half;                      // <= 31
            float vj  = __shfl_sync(0xffffffffu, v,  j);
            int   scj = __shfl_sync(0xffffffffu, sc, j);
            if (j < cnt) {                                       // uniform per half
                float4 hv = __ldg(&h4[(size_t)scj * 16 + f4]);
                acc.x += vj * hv.x; acc.y += vj * hv.y;
                acc.z += vj * hv.z; acc.w += vj * hv.w;
            }
        }
    }

    acc.x += __shfl_xor_sync(0xffffffffu, acc.x, 16);
    acc.y += __shfl_xor_sync(0xffffffffu, acc.y, 16);
    acc.z += __shfl_xor_sync(0xffffffffu, acc.z, 16);
    acc.w += __shfl_xor_sync(0xffffffffu, acc.w, 16);

    if (half == 0) {
        float4 b = __ldg(&bias4[f4]);
        acc.x += b.x; acc.y += b.y; acc.z += b.z; acc.w += b.w;
        out4[(size_t)node * 16 + f4] = acc;
    }
}

// ---------------------------------------------------------------------------
// Launch topology:   default:  [gemm] ----------\
//                    side:     [fill] --(join)---> [agg]
// Fork/join via events: the standard capture-branch pattern. fill overlaps
// gemm (disjoint data); agg waits on both.
// ---------------------------------------------------------------------------
extern "C" void kernel_launch(void* const* d_in, const int* in_sizes, int n_in,
                              void* d_out, int out_size)
{
    const float* x    = (const float*)d_in[0];   // [N, 128]
    const int*   esrc = (const int*)  d_in[1];   // [E]
    const int*   edst = (const int*)  d_in[2];   // [E]
    const float* eval = (const float*)d_in[3];   // [E]
    const float* w    = (const float*)d_in[4];   // [128, 64]
    const float* bias = (const float*)d_in[5];   // [64]
    float* out = (float*)d_out;                  // [N, 64]

    const int n_nodes = in_sizes[0] / D_IN;
    const int n_edges = in_sizes[1];

    float4* h4;
    cudaGetSymbolAddress((void**)&h4, g_h4);
    int* row_start;
    cudaGetSymbolAddress((void**)&row_start, g_row_start);

    cudaStream_t side;
    cudaStreamCreateWithFlags(&side, cudaStreamNonBlocking);
    cudaEvent_t ev_fork, ev_join;
    cudaEventCreateWithFlags(&ev_fork, cudaEventDisableTiming);
    cudaEventCreateWithFlags(&ev_join, cudaEventDisableTiming);

    // fork: side stream branches off the default stream's current front
    cudaEventRecord(ev_fork, 0);
    cudaStreamWaitEvent(side, ev_fork, 0);

    // side branch: row_start fill
    {
        int quads = (n_edges + 3) / 4;
        fill_rowstart_kernel<<<(quads + 255) / 256, 256, 0, side>>>(
            edst, row_start, n_edges, n_nodes);
    }
    cudaEventRecord(ev_join, side);

    // main branch: h = x @ W
    {
        cudaFuncSetAttribute(gemm_tc_kernel,
                             cudaFuncAttributeMaxDynamicSharedMemorySize, GEMM_SMEM);
        int blocks = (n_nodes + 127) / 128;
        gemm_tc_kernel<<<blocks, 256, GEMM_SMEM>>>(x, w, (float*)h4, n_nodes);
    }

    // join: agg needs both h and row_start
    cudaStreamWaitEvent(0, ev_join, 0);
    {
        size_t threads = (size_t)n_nodes * 32;
        agg_kernel<<<(unsigned)((threads + 255) / 256), 256>>>(
            h4, esrc, eval, row_start, (const float4*)bias, (float4*)out, n_nodes);
    }
}

// round 15
// speedup vs baseline: 1.1231x; 1.0997x over previous
#include <cuda_runtime.h>
#include <mma.h>
#include <cstdint>

using namespace nvcuda;

#define N_NODES 50000
#define D_IN    128
#define D_OUT   64
#define FULLM   0xffffffffu

// h scratch: h[row][c] = g_h4[row*16 + c/4]
__device__ float4 g_h4[N_NODES * (D_OUT / 4)];

// ---------------------------------------------------------------------------
// Kernel 1: h = x @ W (tf32 mma.sync) + out=bias init folded in.
// The bias stores are independent streaming writes issued before the MMA
// phase; they hide under tensor work (unlike a dependent scan tail).
// ---------------------------------------------------------------------------
#define XS_LD 132
#define WT_LD 132
#define SMEM_WT_OFF (128 * XS_LD)                       // floats
#define GEMM_SMEM   ((128 * XS_LD + 64 * WT_LD) * 4)    // 101376 B

__global__ __launch_bounds__(256) void gemm_init_kernel(
    const float* __restrict__ x,
    const float* __restrict__ w,
    float* __restrict__ h,
    const float4* __restrict__ bias4,
    float4* __restrict__ out4,
    int n_nodes)
{
    extern __shared__ float sm[];
    float* xs = sm;                  // [128][XS_LD]
    float* wt = sm + SMEM_WT_OFF;    // [64][WT_LD], wt[n][k]

    const int tid = threadIdx.x;
    const int wid = tid >> 5;
    const int row0 = blockIdx.x * 128;

    // ---- stage W^T ----
    #pragma unroll
    for (int i = tid; i < D_IN * D_OUT; i += 256) {
        int k = i >> 6, n = i & 63;
        wt[n * WT_LD + k] = wmma::__float_to_tf32(w[i]);
    }
    // ---- stage x tile ----
    {
        const float4* x4 = (const float4*)x;
        #pragma unroll
        for (int i = tid; i < 128 * 32; i += 256) {
            int r = i >> 5, c4 = i & 31;
            if (row0 + r < n_nodes) {
                float4 v = x4[(size_t)(row0 + r) * 32 + c4];
                float* p = xs + r * XS_LD + c4 * 4;
                p[0] = wmma::__float_to_tf32(v.x);
                p[1] = wmma::__float_to_tf32(v.y);
                p[2] = wmma::__float_to_tf32(v.z);
                p[3] = wmma::__float_to_tf32(v.w);
            }
        }
    }
    // ---- bias init of out rows [row0, row0+128): independent streaming ----
    {
        #pragma unroll
        for (int i = 0; i < 8; i++) {
            int idx = tid + i * 256;          // 0..2047
            int r = idx >> 4, c4 = idx & 15;
            if (row0 + r < n_nodes)
                out4[(size_t)(row0 + r) * 16 + c4] = __ldg(&bias4[c4]);
        }
    }
    __syncthreads();

    const int wrow = row0 + wid * 16;
    if (wrow >= n_nodes) return;    // 50000 % 16 == 0

    wmma::fragment<wmma::accumulator, 16, 16, 8, float> c[4];
    #pragma unroll
    for (int n = 0; n < 4; n++) wmma::fill_fragment(c[n], 0.0f);

    const float* a_base = xs + wid * 16 * XS_LD;

    #pragma unroll
    for (int k = 0; k < 16; k++) {
        wmma::fragment<wmma::matrix_a, 16, 16, 8, wmma::precision::tf32, wmma::row_major> a;
        wmma::load_matrix_sync(a, a_base + k * 8, XS_LD);
        #pragma unroll
        for (int n = 0; n < 4; n++) {
            wmma::fragment<wmma::matrix_b, 16, 16, 8, wmma::precision::tf32, wmma::col_major> b;
            wmma::load_matrix_sync(b, wt + (n * 16) * WT_LD + k * 8, WT_LD);
            wmma::mma_sync(c[n], a, b, c[n]);
        }
    }

    float* hp = h + (size_t)wrow * D_OUT;
    #pragma unroll
    for (int n = 0; n < 4; n++)
        wmma::store_matrix_sync(hp + n * 16, c[n], D_OUT, wmma::mem_row_major);
}

// ---------------------------------------------------------------------------
// Kernel 2: segmented scatter over sorted dst. Warp owns 32 consecutive
// edges; lanes load (dst,src,val) coalesced; halves process even/odd edges
// via shfl broadcast; register-accumulate per dst segment; flush with
// red.global.add.v4.f32 (no memory clobber -> h gathers stay hoistable).
// out pre-initialized to bias by kernel 1.
// ---------------------------------------------------------------------------
__device__ __forceinline__ void red_add_v4(float* p, float4 a) {
    asm volatile("red.global.add.v4.f32 [%0], {%1, %2, %3, %4};"
                 :: "l"(p), "f"(a.x), "f"(a.y), "f"(a.z), "f"(a.w));
}

__global__ __launch_bounds__(256) void scatter_kernel(
    const float4* __restrict__ h4,
    const int*    __restrict__ src,
    const int*    __restrict__ dst,
    const float*  __restrict__ val,
    float*        __restrict__ out,
    int n_edges)
{
    const int lane = threadIdx.x & 31;
    const int f4   = lane & 15;
    const int half = lane >> 4;
    const int warp = (blockIdx.x * blockDim.x + threadIdx.x) >> 5;
    const int e0   = warp * 32;
    if (e0 >= n_edges) return;
    const int cnt = min(32, n_edges - e0);

    // coalesced edge metadata
    int   dv = 0, sv = 0;
    float vv = 0.f;
    if (lane < cnt) {
        const int e = e0 + lane;
        dv = __ldg(&dst[e]);
        sv = __ldg(&src[e]);
        vv = __ldg(&val[e]);
    }

    int cur = __shfl_sync(FULLM, dv, half);   // dst of this half's first edge
    float4 acc = make_float4(0.f, 0.f, 0.f, 0.f);

    #pragma unroll
    for (int jj = 0; jj < 16; jj++) {
        const int j = (jj << 1) | half;
        const int   dj = __shfl_sync(FULLM, dv, j);
        const int   sj = __shfl_sync(FULLM, sv, j);
        const float vj = __shfl_sync(FULLM, vv, j);
        if (j < cnt) {
            if (dj != cur) {                   // uniform per half-warp
                red_add_v4(out + (size_t)cur * D_OUT + f4 * 4, acc);
                acc = make_float4(0.f, 0.f, 0.f, 0.f);
                cur = dj;
            }
            float4 hv = __ldg(&h4[(size_t)sj * 16 + f4]);
            acc.x += vj * hv.x; acc.y += vj * hv.y;
            acc.z += vj * hv.z; acc.w += vj * hv.w;
        }
    }
    red_add_v4(out + (size_t)cur * D_OUT + f4 * 4, acc);
}

// ---------------------------------------------------------------------------
extern "C" void kernel_launch(void* const* d_in, const int* in_sizes, int n_in,
                              void* d_out, int out_size)
{
    const float* x    = (const float*)d_in[0];   // [N, 128]
    const int*   esrc = (const int*)  d_in[1];   // [E]
    const int*   edst = (const int*)  d_in[2];   // [E]
    const float* eval = (const float*)d_in[3];   // [E]
    const float* w    = (const float*)d_in[4];   // [128, 64]
    const float* bias = (const float*)d_in[5];   // [64]
    float* out = (float*)d_out;                  // [N, 64]

    const int n_nodes = in_sizes[0] / D_IN;
    const int n_edges = in_sizes[1];

    float4* h4;
    cudaGetSymbolAddress((void**)&h4, g_h4);

    // 1) h = x @ W, and out = bias
    {
        cudaFuncSetAttribute(gemm_init_kernel,
                             cudaFuncAttributeMaxDynamicSharedMemorySize, GEMM_SMEM);
        int blocks = (n_nodes + 127) / 128;
        gemm_init_kernel<<<blocks, 256, GEMM_SMEM>>>(
            x, w, (float*)h4, (const float4*)bias, (float4*)out, n_nodes);
    }

    // 2) out += A @ h (segmented scatter, vector reductions at boundaries)
    {
        int warps = (n_edges + 31) / 32;
        int threads = warps * 32;
        scatter_kernel<<<(threads + 255) / 256, 256>>>(
            h4, esrc, edst, eval, out, n_edges);
    }
}